// round 13
// baseline (speedup 1.0000x reference)
#include <cuda_runtime.h>
#include <cstdint>
#include <math.h>

#define FULL 0xffffffffu

static constexpr int B_   = 256;
static constexpr int D_   = 128;
static constexpr int DIN_ = 2048;
static constexpr int M_   = 4096;
static constexpr float TAU_INV = 1.0f / 0.07f;

// ---------------- device scratch ----------------
__device__ float g_raw0[B_ * D_];       // K-half 0 partial of emb_raw
__device__ float g_raw1[B_ * D_];       // K-half 1 partial of emb_raw
__device__ float g_acc[2];              // [0]=sum data softplus, [1]=sum noise softplus

// ---------------- A: split-K GEMM with W slice in SMEM -----------------------
// grid 512 = 32 d-slices (4 cols) x 8 b-groups (32 rows) x 2 K-halves (1024).
// 256 threads = 8 warps, 3 blocks/SM. Warp w owns 4 b-rows x 4 d-cols.
// W slice (4 x 1024 fp32 = 16 KB) staged once in static smem.
__global__ void __launch_bounds__(256, 3)
kGemm(const float* __restrict__ outputs,
      const float* __restrict__ W) {
    __shared__ float4 sW4[4 * 256];       // 16 KB
    int ds  = blockIdx.x & 31;            // d-slice 0..31 (4 d each)
    int bgr = (blockIdx.x >> 5) & 7;      // b-group 0..7 (32 b each)
    int ks  = blockIdx.x >> 8;            // K-half 0..1
    int tid = threadIdx.x, w = tid >> 5, lane = tid & 31;

    // stage W rows [ds*4, ds*4+4), cols [ks*1024, +1024) -- 4 float4/thread
    {
        const float4* w4 = (const float4*)W;
#pragma unroll
        for (int i = 0; i < 4; i++) {
            int idx = i * 256 + tid;
            int row = idx >> 8, c4 = idx & 255;
            sW4[idx] = w4[(size_t)(ds * 4 + row) * (DIN_ / 4) + ks * 256 + c4];
        }
    }
    __syncthreads();

    // mainloop: 4 b-rows per warp, 4 d each, K=1024 via 8 iters of 128
    int b0 = bgr * 32 + w * 4;
    const float4* o4 = (const float4*)outputs;

    float acc[4][4];
#pragma unroll
    for (int bi = 0; bi < 4; bi++)
#pragma unroll
        for (int dd = 0; dd < 4; dd++) acc[bi][dd] = 0.0f;

#pragma unroll 2
    for (int it = 0; it < 8; it++) {
        float4 ov[4];
#pragma unroll
        for (int bi = 0; bi < 4; bi++)
            ov[bi] = o4[(size_t)(b0 + bi) * (DIN_ / 4) + ks * 256 + it * 32 + lane];
#pragma unroll
        for (int dd = 0; dd < 4; dd++) {
            float4 wv = sW4[dd * 256 + it * 32 + lane];
#pragma unroll
            for (int bi = 0; bi < 4; bi++) {
                float a = acc[bi][dd];
                a = fmaf(wv.x, ov[bi].x, a);
                a = fmaf(wv.y, ov[bi].y, a);
                a = fmaf(wv.z, ov[bi].z, a);
                a = fmaf(wv.w, ov[bi].w, a);
                acc[bi][dd] = a;
            }
        }
    }

    // reduce all 16 accs across lanes; lane bi*4+dd keeps its value
    float mine = 0.0f;
#pragma unroll
    for (int bi = 0; bi < 4; bi++)
#pragma unroll
        for (int dd = 0; dd < 4; dd++) {
            float r = acc[bi][dd];
#pragma unroll
            for (int o = 16; o; o >>= 1) r += __shfl_xor_sync(FULL, r, o);
            if (lane == bi * 4 + dd) mine = r;
        }

    if (lane < 16) {
        int dd_l = lane & 3, bi_l = lane >> 2;
        int d = ds * 4 + dd_l;
        int b = b0 + bi_l;
        float* dst = ks ? g_raw1 : g_raw0;
        dst[b * D_ + d] = mine;
    }

    if (blockIdx.x == 0 && tid == 0) { g_acc[0] = 0.0f; g_acc[1] = 0.0f; }
}

// ---------------- B: main gather + logsumexp + losses + entries --------------
// One block per batch row. 16 warps; warp w handles negs [w*256, w*256+256).
// Prologue combines the two K-half partials + bias and normalizes.
__global__ void __launch_bounds__(512, 2) kMain(
    const float* __restrict__ mbank,
    const float* __restrict__ bias,
    const int*   __restrict__ indices,
    const int*   __restrict__ ridx,
    float*       __restrict__ out) {
    int b = blockIdx.x;
    int tid = threadIdx.x, w = tid >> 5, lane = tid & 31;

    __shared__ float sneg[M_];
    __shared__ float sr[33];

    // e = l2norm(raw0 + raw1 + bias)   (each warp redundantly, L1-cached)
    float4 r0 = ((const float4*)g_raw0)[b * 32 + lane];
    float4 r1 = ((const float4*)g_raw1)[b * 32 + lane];
    float4 bv = ((const float4*)bias)[lane];
    float4 e;
    e.x = r0.x + r1.x + bv.x;
    e.y = r0.y + r1.y + bv.y;
    e.z = r0.z + r1.z + bv.z;
    e.w = r0.w + r1.w + bv.w;
    float ssq = e.x * e.x + e.y * e.y + e.z * e.z + e.w * e.w;
#pragma unroll
    for (int o = 16; o; o >>= 1) ssq += __shfl_xor_sync(FULL, ssq, o);
    float inv = 1.0f / fmaxf(sqrtf(ssq), 1e-12f);
    e.x *= inv; e.y *= inv; e.z *= inv; e.w *= inv;

    const float4* mb4 = (const float4*)mbank;
    const int* ri = ridx + (size_t)b * M_;

    // ---- gather + dot: 256 negs per warp ----
    int m0 = w * 256;
    for (int mb_ = m0; mb_ < m0 + 256; mb_ += 32) {
        int myIdx = ri[mb_ + lane];
#pragma unroll 8
        for (int j = 0; j < 32; j++) {
            int idx = __shfl_sync(FULL, myIdx, j);
            float4 v = mb4[(size_t)idx * 32 + lane];
            float d = v.x * e.x + v.y * e.y;
            d = fmaf(v.z, e.z, d);
            d = fmaf(v.w, e.w, d);
#pragma unroll
            for (int o = 16; o; o >>= 1) d += __shfl_xor_sync(FULL, d, o);
            if (lane == j) sneg[mb_ + j] = d * TAU_INV;
        }
    }
    __syncthreads();

    // ---- each thread owns 8 negs (stride 512, conflict-free) ----
    float vl[8];
    float mx = -3.0e38f;
#pragma unroll
    for (int i = 0; i < 8; i++) {
        vl[i] = sneg[tid + i * 512];
        mx = fmaxf(mx, vl[i]);
    }
#pragma unroll
    for (int o = 16; o; o >>= 1) mx = fmaxf(mx, __shfl_xor_sync(FULL, mx, o));
    if (lane == 0) sr[w] = mx;
    __syncthreads();
    if (w == 0) {
        float t2 = sr[lane & 15];
#pragma unroll
        for (int o = 8; o; o >>= 1) t2 = fmaxf(t2, __shfl_xor_sync(FULL, t2, o));
        if (lane == 0) sr[32] = t2;
    }
    __syncthreads();
    float Mx = sr[32];

    float se = 0.f;
#pragma unroll
    for (int i = 0; i < 8; i++) se += __expf(vl[i] - Mx);
#pragma unroll
    for (int o = 16; o; o >>= 1) se += __shfl_xor_sync(FULL, se, o);
    __syncthreads();
    if (lane == 0) sr[w] = se;
    __syncthreads();
    if (w == 0) {
        float t2 = (lane < 16) ? sr[lane] : 0.f;
#pragma unroll
        for (int o = 8; o; o >>= 1) t2 += __shfl_xor_sync(FULL, t2, o);
        if (lane == 0) sr[32] = Mx + __logf(t2);
    }
    __syncthreads();
    float logC = sr[32];

    // noise loss: sum softplus(neg - logC)
    float ns = 0.f;
#pragma unroll
    for (int i = 0; i < 8; i++) {
        float x = vl[i] - logC;
        ns += (x > 15.f) ? x : log1pf(__expf(x));
    }
#pragma unroll
    for (int o = 16; o; o >>= 1) ns += __shfl_xor_sync(FULL, ns, o);
    __syncthreads();
    if (lane == 0) sr[w] = ns;
    __syncthreads();
    if (w == 0) {
        float t2 = (lane < 16) ? sr[lane] : 0.f;
#pragma unroll
        for (int o = 8; o; o >>= 1) t2 += __shfl_xor_sync(FULL, t2, o);
        if (lane == 0) atomicAdd(&g_acc[1], t2);
    }

    // ---- warp 0: positive term + entries ----
    if (w == 0) {
        int pidx = indices[b];
        float4 p = mb4[(size_t)pidx * 32 + lane];
        float d = p.x * e.x + p.y * e.y;
        d = fmaf(p.z, e.z, d);
        d = fmaf(p.w, e.w, d);
#pragma unroll
        for (int o = 16; o; o >>= 1) d += __shfl_xor_sync(FULL, d, o);
        float pos = d * TAU_INV;

        float4 ent;
        ent.x = 0.5f * (p.x + e.x);
        ent.y = 0.5f * (p.y + e.y);
        ent.z = 0.5f * (p.z + e.z);
        ent.w = 0.5f * (p.w + e.w);
        float nsq = ent.x * ent.x + ent.y * ent.y + ent.z * ent.z + ent.w * ent.w;
#pragma unroll
        for (int o = 16; o; o >>= 1) nsq += __shfl_xor_sync(FULL, nsq, o);
        float inv2 = 1.0f / fmaxf(sqrtf(nsq), 1e-12f);
        ent.x *= inv2; ent.y *= inv2; ent.z *= inv2; ent.w *= inv2;

        int base = 1 + b * D_ + lane * 4;
        out[base + 0] = ent.x;
        out[base + 1] = ent.y;
        out[base + 2] = ent.z;
        out[base + 3] = ent.w;

        if (lane == 0) {
            float x = logC - pos;
            float dl = (x > 15.f) ? x : log1pf(__expf(x));
            atomicAdd(&g_acc[0], dl);
        }
    }
}

// ---------------- C: finalize scalars ----------------------------------------
__global__ void kFinal(float* __restrict__ out) {
    float dl = g_acc[0] * (1.0f / (float)B_);
    float nl = g_acc[1] * (1.0f / (float)B_);
    out[0] = dl + nl;
    out[1 + B_ * D_]     = dl;
    out[1 + B_ * D_ + 1] = nl;
}

// ---------------- launcher ----------------------------------------------------
extern "C" void kernel_launch(void* const* d_in, const int* in_sizes, int n_in,
                              void* d_out, int out_size) {
    const float* outputs = (const float*)d_in[0];
    const float* W       = (const float*)d_in[1];
    const float* bias    = (const float*)d_in[2];
    const float* mbank   = (const float*)d_in[3];
    const int*   indices = (const int*)d_in[4];
    const int*   ridx    = (const int*)d_in[5];
    float* out = (float*)d_out;

    kGemm<<<512, 256>>>(outputs, W);
    kMain<<<256, 512>>>(mbank, bias, indices, ridx, out);
    kFinal<<<1, 1>>>(out);
}

// round 14
// speedup vs baseline: 1.0110x; 1.0110x over previous
#include <cuda_runtime.h>
#include <cstdint>
#include <math.h>

#define FULL 0xffffffffu

static constexpr int B_   = 256;
static constexpr int D_   = 128;
static constexpr int DIN_ = 2048;
static constexpr int M_   = 4096;
static constexpr float TAU_INV = 1.0f / 0.07f;

// ---------------- device scratch ----------------
__device__ float g_raw[B_ * D_];        // un-normalized emb (+bias), 128 KB
__device__ float g_pssq[B_ * 32];       // per-d-slice partial sum-of-squares
__device__ float g_acc[2];              // [0]=sum data softplus, [1]=sum noise softplus

// ---------------- A: GEMM with W slice in SMEM (best config, R9) -------------
// grid 256 = 32 d-slices (4 cols) x 8 b-groups (32 rows). 256 threads = 8 warps.
__global__ void __launch_bounds__(256, 2)
kGemm(const float* __restrict__ outputs,
      const float* __restrict__ W,
      const float* __restrict__ bias) {
    __shared__ float4 sW4[4 * 512];       // 32 KB
    int ds  = blockIdx.x & 31;            // d-slice 0..31 (4 d each)
    int bgr = blockIdx.x >> 5;            // b-group 0..7 (32 b each)
    int tid = threadIdx.x, w = tid >> 5, lane = tid & 31;

    // stage W rows [ds*4, ds*4+4) -- coalesced, 8 float4 per thread
    {
        const float4* src = (const float4*)W + (size_t)(ds * 4) * (DIN_ / 4);
#pragma unroll
        for (int i = 0; i < 8; i++)
            sW4[i * 256 + tid] = src[i * 256 + tid];
    }
    __syncthreads();

    // allow the dependent kernel (kMain) to start launching now; its
    // consumption of our stores is gated by cudaGridDependencySynchronize().
    cudaTriggerProgrammaticLaunchCompletion();

    // mainloop: 4 b-rows per warp, 4 d each, K=2048 via 16 iters of 128
    int b0 = bgr * 32 + w * 4;
    const float4* o4 = (const float4*)outputs;

    float acc[4][4];
#pragma unroll
    for (int bi = 0; bi < 4; bi++)
#pragma unroll
        for (int dd = 0; dd < 4; dd++) acc[bi][dd] = 0.0f;

#pragma unroll 4
    for (int it = 0; it < 16; it++) {
        float4 ov[4];
#pragma unroll
        for (int bi = 0; bi < 4; bi++)
            ov[bi] = o4[(size_t)(b0 + bi) * (DIN_ / 4) + it * 32 + lane];
#pragma unroll
        for (int dd = 0; dd < 4; dd++) {
            float4 wv = sW4[dd * 512 + it * 32 + lane];
#pragma unroll
            for (int bi = 0; bi < 4; bi++) {
                float a = acc[bi][dd];
                a = fmaf(wv.x, ov[bi].x, a);
                a = fmaf(wv.y, ov[bi].y, a);
                a = fmaf(wv.z, ov[bi].z, a);
                a = fmaf(wv.w, ov[bi].w, a);
                acc[bi][dd] = a;
            }
        }
    }

    // reduce all 16 accs across lanes; lane bi*4+dd keeps its value
    float mine = 0.0f;
#pragma unroll
    for (int bi = 0; bi < 4; bi++)
#pragma unroll
        for (int dd = 0; dd < 4; dd++) {
            float r = acc[bi][dd];
#pragma unroll
            for (int o = 16; o; o >>= 1) r += __shfl_xor_sync(FULL, r, o);
            if (lane == bi * 4 + dd) mine = r;
        }

    if (lane < 16) {
        int dd_l = lane & 3, bi_l = lane >> 2;
        int d = ds * 4 + dd_l;
        int b = b0 + bi_l;
        mine += bias[d];
        g_raw[b * D_ + d] = mine;

        // partial sum-of-squares over this slice's 4 d (4-lane groups)
        float sq = mine * mine;
        sq += __shfl_xor_sync(0x0000ffffu, sq, 1);
        sq += __shfl_xor_sync(0x0000ffffu, sq, 2);
        if (dd_l == 0) g_pssq[b * 32 + ds] = sq;
    }

    if (blockIdx.x == 0 && tid == 0) { g_acc[0] = 0.0f; g_acc[1] = 0.0f; }
}

// ---------------- B: main gather + logsumexp + losses + entries --------------
// One block per batch row. 16 warps; warp w handles negs [w*256, w*256+256).
// PDL: stash all neg indices BEFORE the grid dependency sync so index traffic
// overlaps kGemm; only the g_raw/g_pssq reads wait.
__global__ void __launch_bounds__(512, 2) kMain(
    const float* __restrict__ mbank,
    const int*   __restrict__ indices,
    const int*   __restrict__ ridx,
    float*       __restrict__ out) {
    int b = blockIdx.x;
    int tid = threadIdx.x, w = tid >> 5, lane = tid & 31;

    __shared__ float sneg[M_];
    __shared__ float sr[33];

    const int* ri = ridx + (size_t)b * M_;
    int m0 = w * 256;

    // ---- pre-dependency work: stash this warp's 256 neg indices ----
    int idxs[8];
#pragma unroll
    for (int i = 0; i < 8; i++)
        idxs[i] = ri[m0 + i * 32 + lane];
    int pidx0 = (w == 0) ? indices[b] : 0;

    // wait for kGemm's stores to be visible
    cudaGridDependencySynchronize();

    // normalize e on load: ssq = sum of 32 slice partials
    float ssq = g_pssq[b * 32 + lane];
#pragma unroll
    for (int o = 16; o; o >>= 1) ssq += __shfl_xor_sync(FULL, ssq, o);
    float inv = 1.0f / fmaxf(sqrtf(ssq), 1e-12f);

    float4 e = ((const float4*)g_raw)[b * 32 + lane];
    e.x *= inv; e.y *= inv; e.z *= inv; e.w *= inv;

    const float4* mb4 = (const float4*)mbank;

    // ---- gather + dot: 256 negs per warp ----
#pragma unroll
    for (int t = 0; t < 8; t++) {
        int myIdx = idxs[t];
        int mb_ = m0 + t * 32;
#pragma unroll 8
        for (int j = 0; j < 32; j++) {
            int idx = __shfl_sync(FULL, myIdx, j);
            float4 v = mb4[(size_t)idx * 32 + lane];
            float d = v.x * e.x + v.y * e.y;
            d = fmaf(v.z, e.z, d);
            d = fmaf(v.w, e.w, d);
#pragma unroll
            for (int o = 16; o; o >>= 1) d += __shfl_xor_sync(FULL, d, o);
            if (lane == j) sneg[mb_ + j] = d * TAU_INV;
        }
    }
    __syncthreads();

    // ---- each thread owns 8 negs (stride 512, conflict-free) ----
    float vl[8];
    float mx = -3.0e38f;
#pragma unroll
    for (int i = 0; i < 8; i++) {
        vl[i] = sneg[tid + i * 512];
        mx = fmaxf(mx, vl[i]);
    }
#pragma unroll
    for (int o = 16; o; o >>= 1) mx = fmaxf(mx, __shfl_xor_sync(FULL, mx, o));
    if (lane == 0) sr[w] = mx;
    __syncthreads();
    if (w == 0) {
        float t2 = sr[lane & 15];
#pragma unroll
        for (int o = 8; o; o >>= 1) t2 = fmaxf(t2, __shfl_xor_sync(FULL, t2, o));
        if (lane == 0) sr[32] = t2;
    }
    __syncthreads();
    float Mx = sr[32];

    float se = 0.f;
#pragma unroll
    for (int i = 0; i < 8; i++) se += __expf(vl[i] - Mx);
#pragma unroll
    for (int o = 16; o; o >>= 1) se += __shfl_xor_sync(FULL, se, o);
    __syncthreads();
    if (lane == 0) sr[w] = se;
    __syncthreads();
    if (w == 0) {
        float t2 = (lane < 16) ? sr[lane] : 0.f;
#pragma unroll
        for (int o = 8; o; o >>= 1) t2 += __shfl_xor_sync(FULL, t2, o);
        if (lane == 0) sr[32] = Mx + __logf(t2);
    }
    __syncthreads();
    float logC = sr[32];

    // noise loss: sum softplus(neg - logC)
    float ns = 0.f;
#pragma unroll
    for (int i = 0; i < 8; i++) {
        float x = vl[i] - logC;
        ns += (x > 15.f) ? x : log1pf(__expf(x));
    }
#pragma unroll
    for (int o = 16; o; o >>= 1) ns += __shfl_xor_sync(FULL, ns, o);
    __syncthreads();
    if (lane == 0) sr[w] = ns;
    __syncthreads();
    if (w == 0) {
        float t2 = (lane < 16) ? sr[lane] : 0.f;
#pragma unroll
        for (int o = 8; o; o >>= 1) t2 += __shfl_xor_sync(FULL, t2, o);
        if (lane == 0) atomicAdd(&g_acc[1], t2);
    }

    // ---- warp 0: positive term + entries ----
    if (w == 0) {
        float4 p = mb4[(size_t)pidx0 * 32 + lane];
        float d = p.x * e.x + p.y * e.y;
        d = fmaf(p.z, e.z, d);
        d = fmaf(p.w, e.w, d);
#pragma unroll
        for (int o = 16; o; o >>= 1) d += __shfl_xor_sync(FULL, d, o);
        float pos = d * TAU_INV;

        float4 ent;
        ent.x = 0.5f * (p.x + e.x);
        ent.y = 0.5f * (p.y + e.y);
        ent.z = 0.5f * (p.z + e.z);
        ent.w = 0.5f * (p.w + e.w);
        float nsq = ent.x * ent.x + ent.y * ent.y + ent.z * ent.z + ent.w * ent.w;
#pragma unroll
        for (int o = 16; o; o >>= 1) nsq += __shfl_xor_sync(FULL, nsq, o);
        float inv2 = 1.0f / fmaxf(sqrtf(nsq), 1e-12f);
        ent.x *= inv2; ent.y *= inv2; ent.z *= inv2; ent.w *= inv2;

        int base = 1 + b * D_ + lane * 4;
        out[base + 0] = ent.x;
        out[base + 1] = ent.y;
        out[base + 2] = ent.z;
        out[base + 3] = ent.w;

        if (lane == 0) {
            float x = logC - pos;
            float dl = (x > 15.f) ? x : log1pf(__expf(x));
            atomicAdd(&g_acc[0], dl);
        }
    }
}

// ---------------- C: finalize scalars ----------------------------------------
__global__ void kFinal(float* __restrict__ out) {
    float dl = g_acc[0] * (1.0f / (float)B_);
    float nl = g_acc[1] * (1.0f / (float)B_);
    out[0] = dl + nl;
    out[1 + B_ * D_]     = dl;
    out[1 + B_ * D_ + 1] = nl;
}

// ---------------- launcher ----------------------------------------------------
extern "C" void kernel_launch(void* const* d_in, const int* in_sizes, int n_in,
                              void* d_out, int out_size) {
    const float* outputs = (const float*)d_in[0];
    const float* W       = (const float*)d_in[1];
    const float* bias    = (const float*)d_in[2];
    const float* mbank   = (const float*)d_in[3];
    const int*   indices = (const int*)d_in[4];
    const int*   ridx    = (const int*)d_in[5];
    float* out = (float*)d_out;

    kGemm<<<256, 256>>>(outputs, W, bias);

    // kMain with programmatic dependent launch: may begin (index loads)
    // while kGemm is still running; gridDependencySynchronize gates g_raw.
    {
        cudaLaunchConfig_t cfg = {};
        cfg.gridDim  = dim3(256, 1, 1);
        cfg.blockDim = dim3(512, 1, 1);
        cfg.dynamicSmemBytes = 0;
        cfg.stream = 0;
        cudaLaunchAttribute attr[1];
        attr[0].id = cudaLaunchAttributeProgrammaticStreamSerialization;
        attr[0].val.programmaticStreamSerializationAllowed = 1;
        cfg.attrs = attr;
        cfg.numAttrs = 1;
        cudaLaunchKernelEx(&cfg, kMain, mbank, indices, ridx, out);
    }

    kFinal<<<1, 1>>>(out);
}